// round 1
// baseline (speedup 1.0000x reference)
#include <cuda_runtime.h>
#include <cuda_bf16.h>
#include <math.h>

// Problem constants
#define XYDIM 16
#define ZDIM  16
#define SNUM  4096     // 16*16*16
#define VNUM  2048
#define BNUM  8
#define LNUM  32
#define WNUM  8

#define LOG5F 1.6094379124341003f

// ---------------- scratch (device globals: no allocation allowed) ----------------
__device__ float g_lse[SNUM];                      // row logsumexp of emis_w
__device__ float g_LQT[(size_t)VNUM * SNUM];       // smoothed log-emission, TRANSPOSED [v][s]  (32MB)
__device__ float g_allemis[LNUM * BNUM * SNUM];    // (L,B,S) emission sums (4MB)
__device__ float g_P7[7 * SNUM];                   // exp(logp - amax), fixed-offset slots, [k][s]
__device__ float g_amax[SNUM];
__device__ float g_plse[1];                        // prior logsumexp

// ---------------- K1: per-row logsumexp of emis_w ----------------
__global__ void k_row_lse(const float* __restrict__ emis) {
    int s = blockIdx.x;
    const float4* row = reinterpret_cast<const float4*>(emis + (size_t)s * VNUM);
    int t = threadIdx.x;                 // 256 threads, 8 floats each
    float4 a = row[t];
    float4 b = row[t + 256];
    float mx = fmaxf(fmaxf(fmaxf(a.x, a.y), fmaxf(a.z, a.w)),
                     fmaxf(fmaxf(b.x, b.y), fmaxf(b.z, b.w)));
    __shared__ float red[8];
    #pragma unroll
    for (int o = 16; o; o >>= 1) mx = fmaxf(mx, __shfl_xor_sync(0xffffffffu, mx, o));
    if ((t & 31) == 0) red[t >> 5] = mx;
    __syncthreads();
    mx = red[0];
    #pragma unroll
    for (int k = 1; k < 8; k++) mx = fmaxf(mx, red[k]);
    float se = expf(a.x - mx) + expf(a.y - mx) + expf(a.z - mx) + expf(a.w - mx)
             + expf(b.x - mx) + expf(b.y - mx) + expf(b.z - mx) + expf(b.w - mx);
    #pragma unroll
    for (int o = 16; o; o >>= 1) se += __shfl_xor_sync(0xffffffffu, se, o);
    __syncthreads();
    if ((t & 31) == 0) red[t >> 5] = se;
    __syncthreads();
    if (t == 0) {
        float sum = 0.f;
        #pragma unroll
        for (int k = 0; k < 8; k++) sum += red[k];
        g_lse[s] = mx + logf(sum);
    }
}

// ---------------- K2: 5-point (y,x) smoothing -> transposed log table ----------------
// block = (vchunk of 32, z-plane). Load 256x32 probs into smem (exp once per element),
// stencil from smem, write LQT[v][s] coalesced.
__global__ void k_smooth(const float* __restrict__ emis) {
    __shared__ float sm[256][33];        // padded: conflict-free both phases
    int v0 = blockIdx.x * 32;
    int z  = blockIdx.y;
    int t = threadIdx.x;                 // 256 threads
    int w = t >> 5, l = t & 31;
    int sbase = z * 256;
    // each warp loads 32 rows, one float per lane (128B coalesced per access)
    #pragma unroll 4
    for (int rr = 0; rr < 32; rr++) {
        int r = w * 32 + rr;
        int s = sbase + r;
        float x = emis[(size_t)s * VNUM + v0 + l];
        sm[r][l] = expf(x - g_lse[s]);
    }
    __syncthreads();
    int p = t;
    int x = p & 15, y = p >> 4;
    int pu = (y < 15) ? p + 16 : p;      // up:   em[min(y+1,15), x]
    int pd = (y > 0)  ? p - 16 : p;      // down: em[max(y-1,0), x]
    int pl = (x < 15) ? p + 1  : p;      // lf:   em[y, min(x+1,15)]
    int pr = (x > 0)  ? p - 1  : p;      // rt:   em[y, max(x-1,0)]
    #pragma unroll 4
    for (int i = 0; i < 32; i++) {
        float Q = sm[p][i] + sm[pu][i] + sm[pd][i] + sm[pl][i] + sm[pr][i];
        g_LQT[(size_t)(v0 + i) * SNUM + sbase + p] = logf(Q) - LOG5F;
    }
}

// ---------------- K3: token gather-sum -> all_emis (L,B,S) ----------------
__global__ void k_gather(const int* __restrict__ stories) {
    int b = blockIdx.x, l = blockIdx.y;
    __shared__ int tok[WNUM];
    if (threadIdx.x < WNUM) tok[threadIdx.x] = stories[(b * LNUM + l) * WNUM + threadIdx.x];
    __syncthreads();
    int t = threadIdx.x;                 // 256 threads, 16 states each
    float* dst = g_allemis + ((size_t)l * BNUM + b) * SNUM;
    #pragma unroll 4
    for (int i = 0; i < 16; i++) {
        int s = i * 256 + t;
        float acc = 0.f;
        #pragma unroll
        for (int w2 = 0; w2 < WNUM; w2++) {
            int tk = tok[w2];
            if (tk < VNUM) acc += g_LQT[(size_t)tk * SNUM + s];
        }
        dst[s] = acc;
    }
}

// ---------------- K4: transition log-softmax with stable valid-first pairing ----------------
// trans_w[s,k] pairs with the k-th VALID offset (original offset order).
// Store P7 in FIXED offset slots {0,+1,-1,+16,-16,+256,+512} so K5 uses constant deltas.
__global__ void k_trans(const float* __restrict__ tw) {
    int j = blockIdx.x * 256 + threadIdx.x;
    int x = j & 15, y = (j >> 4) & 15, z = j >> 8;
    bool val[7] = { true, x < 15, x > 0, y < 15, y > 0, z < 15, z < 14 };
    float wv[7];
    int r = 0;
    float M = -INFINITY;
    #pragma unroll
    for (int i = 0; i < 7; i++) {
        if (val[i]) { wv[i] = tw[j * 7 + r]; r++; M = fmaxf(M, wv[i]); }
        else wv[i] = 0.f;
    }
    float sum = 0.f;
    #pragma unroll
    for (int i = 0; i < 7; i++) if (val[i]) sum += expf(wv[i] - M);
    g_amax[j] = -logf(sum);
    #pragma unroll
    for (int i = 0; i < 7; i++)
        g_P7[i * SNUM + j] = val[i] ? expf(wv[i] - M) : 0.f;
}

// ---------------- K4b: prior logsumexp ----------------
__global__ void k_prior(const float* __restrict__ pw) {
    int t = threadIdx.x;                 // 1024 threads, 4 elems each
    float v0 = pw[t], v1 = pw[t + 1024], v2 = pw[t + 2048], v3 = pw[t + 3072];
    float mx = fmaxf(fmaxf(v0, v1), fmaxf(v2, v3));
    __shared__ float red[32];
    #pragma unroll
    for (int o = 16; o; o >>= 1) mx = fmaxf(mx, __shfl_xor_sync(0xffffffffu, mx, o));
    if ((t & 31) == 0) red[t >> 5] = mx;
    __syncthreads();
    mx = red[0];
    #pragma unroll
    for (int k = 1; k < 32; k++) mx = fmaxf(mx, red[k]);
    float se = expf(v0 - mx) + expf(v1 - mx) + expf(v2 - mx) + expf(v3 - mx);
    #pragma unroll
    for (int o = 16; o; o >>= 1) se += __shfl_xor_sync(0xffffffffu, se, o);
    __syncthreads();
    if ((t & 31) == 0) red[t >> 5] = se;
    __syncthreads();
    if (t == 0) {
        float sum = 0.f;
        #pragma unroll
        for (int k = 0; k < 32; k++) sum += red[k];
        g_plse[0] = mx + logf(sum);
    }
}

// ---------------- K5: forward recursion, one CTA per batch chain ----------------
__global__ void __launch_bounds__(512, 1)
k_forward(const float* __restrict__ pw, float* __restrict__ out) {
    __shared__ float sc[SNUM];
    __shared__ float sp[SNUM];
    __shared__ float red[16];
    int b = blockIdx.x;
    int t = threadIdx.x;                 // 512 threads, 8 states each (strided)
    int wid = t >> 5, lane = t & 31;

    // persistent per-thread transition rows (coalesced loads: [k][s] layout)
    float p7r[8][7], amr[8];
    #pragma unroll
    for (int st = 0; st < 8; st++) {
        int j = t + 512 * st;
        #pragma unroll
        for (int k = 0; k < 7; k++) p7r[st][k] = g_P7[k * SNUM + j];
        amr[st] = g_amax[j];
    }
    float plse = g_plse[0];

    // l = 0: score0 = all_emis[0] + log_softmax(prior)
    float lm = -INFINITY;
    #pragma unroll
    for (int st = 0; st < 8; st++) {
        int j = t + 512 * st;
        float v = g_allemis[(size_t)b * SNUM + j] + (pw[j] - plse);
        sc[j] = v;
        out[(size_t)b * SNUM + j] = v;
        lm = fmaxf(lm, v);
    }
    #pragma unroll
    for (int o = 16; o; o >>= 1) lm = fmaxf(lm, __shfl_xor_sync(0xffffffffu, lm, o));
    if (lane == 0) red[wid] = lm;
    __syncthreads();
    float m = red[0];
    #pragma unroll
    for (int k = 1; k < 16; k++) m = fmaxf(m, red[k]);

    for (int l = 1; l < LNUM; l++) {
        float emt[8];
        // phase A: sp = exp(score - m); prefetch this step's emissions
        #pragma unroll
        for (int st = 0; st < 8; st++) {
            int j = t + 512 * st;
            sp[j] = expf(sc[j] - m);
            emt[st] = g_allemis[((size_t)l * BNUM + b) * SNUM + j];
        }
        __syncthreads();
        // phase B: 7-neighbor gather + log; invalid slots carry P7==0 so masked
        // addresses just wrap (&4095) — sp values are finite, 0*x == 0.
        float lm2 = -INFINITY;
        #pragma unroll
        for (int st = 0; st < 8; st++) {
            int j = t + 512 * st;
            float acc = p7r[st][0] * sp[j]
                      + p7r[st][1] * sp[(j + 1)   & (SNUM - 1)]
                      + p7r[st][2] * sp[(j - 1)   & (SNUM - 1)]
                      + p7r[st][3] * sp[(j + 16)  & (SNUM - 1)]
                      + p7r[st][4] * sp[(j - 16)  & (SNUM - 1)]
                      + p7r[st][5] * sp[(j + 256) & (SNUM - 1)]
                      + p7r[st][6] * sp[(j + 512) & (SNUM - 1)];
            float v = emt[st] + logf(acc) + m + amr[st];
            sc[j] = v;
            out[((size_t)l * BNUM + b) * SNUM + j] = v;
            lm2 = fmaxf(lm2, v);
        }
        #pragma unroll
        for (int o = 16; o; o >>= 1) lm2 = fmaxf(lm2, __shfl_xor_sync(0xffffffffu, lm2, o));
        if (lane == 0) red[wid] = lm2;
        __syncthreads();
        m = red[0];
        #pragma unroll
        for (int k = 1; k < 16; k++) m = fmaxf(m, red[k]);
    }
}

// ---------------- launch ----------------
extern "C" void kernel_launch(void* const* d_in, const int* in_sizes, int n_in,
                              void* d_out, int out_size) {
    const int*   stories = nullptr;
    const float* trans_w = nullptr;
    const float* emis_w  = nullptr;
    const float* prior_w = nullptr;
    for (int i = 0; i < n_in; i++) {
        switch (in_sizes[i]) {
            case BNUM * LNUM * WNUM: stories = (const int*)d_in[i];   break; // 2048
            case SNUM * 7:           trans_w = (const float*)d_in[i]; break; // 28672
            case SNUM * VNUM:        emis_w  = (const float*)d_in[i]; break; // 8388608
            case SNUM:               prior_w = (const float*)d_in[i]; break; // 4096
            default: break; // story_length scalar
        }
    }
    float* out = (float*)d_out;

    k_row_lse<<<SNUM, 256>>>(emis_w);
    k_smooth<<<dim3(VNUM / 32, ZDIM), 256>>>(emis_w);
    k_gather<<<dim3(BNUM, LNUM), 256>>>(stories);
    k_trans<<<SNUM / 256, 256>>>(trans_w);
    k_prior<<<1, 1024>>>(prior_w);
    k_forward<<<BNUM, 512>>>(prior_w, out);
}

// round 2
// speedup vs baseline: 1.5946x; 1.5946x over previous
#include <cuda_runtime.h>
#include <cuda_bf16.h>
#include <math.h>

// Problem constants
#define XYDIM 16
#define ZDIM  16
#define SNUM  4096     // 16*16*16
#define VNUM  2048
#define BNUM  8
#define LNUM  32
#define WNUM  8

#define LOG5F 1.6094379124341003f

// ---------------- scratch (device globals: no allocation allowed) ----------------
__device__ float g_lse[SNUM];                      // row logsumexp of emis_w
__device__ float g_LQT[(size_t)VNUM * SNUM];       // smoothed log-emission, TRANSPOSED [v][s]  (32MB)
__device__ float g_allemis[LNUM * BNUM * SNUM];    // (L,B,S) emission sums (4MB)
__device__ float g_P7[7 * SNUM];                   // exp(logp - amax), fixed-offset slots, [k][s]
__device__ float g_amax[SNUM];
__device__ float g_plse[1];                        // prior logsumexp

// ---------------- K_prep: fused row-lse (4096 blocks) + trans (16) + prior (1) ----------------
__global__ void k_prep(const float* __restrict__ emis,
                       const float* __restrict__ tw,
                       const float* __restrict__ pw) {
    int bid = blockIdx.x;
    int t = threadIdx.x;                 // 256 threads

    if (bid < SNUM) {
        // ---- per-row logsumexp of emis_w ----
        int s = bid;
        const float4* row = reinterpret_cast<const float4*>(emis + (size_t)s * VNUM);
        float4 a = row[t];
        float4 b = row[t + 256];
        float mx = fmaxf(fmaxf(fmaxf(a.x, a.y), fmaxf(a.z, a.w)),
                         fmaxf(fmaxf(b.x, b.y), fmaxf(b.z, b.w)));
        __shared__ float red[8];
        #pragma unroll
        for (int o = 16; o; o >>= 1) mx = fmaxf(mx, __shfl_xor_sync(0xffffffffu, mx, o));
        if ((t & 31) == 0) red[t >> 5] = mx;
        __syncthreads();
        mx = red[0];
        #pragma unroll
        for (int k = 1; k < 8; k++) mx = fmaxf(mx, red[k]);
        float se = __expf(a.x - mx) + __expf(a.y - mx) + __expf(a.z - mx) + __expf(a.w - mx)
                 + __expf(b.x - mx) + __expf(b.y - mx) + __expf(b.z - mx) + __expf(b.w - mx);
        #pragma unroll
        for (int o = 16; o; o >>= 1) se += __shfl_xor_sync(0xffffffffu, se, o);
        __syncthreads();
        if ((t & 31) == 0) red[t >> 5] = se;
        __syncthreads();
        if (t == 0) {
            float sum = 0.f;
            #pragma unroll
            for (int k = 0; k < 8; k++) sum += red[k];
            g_lse[s] = mx + __logf(sum);
        }
    } else if (bid < SNUM + 16) {
        // ---- transition log-softmax with stable valid-first pairing ----
        // trans_w[s,k] pairs with the k-th VALID offset (original offset order).
        // P7 stored in FIXED offset slots {0,+1,-1,+16,-16,+256,+512}.
        int j = (bid - SNUM) * 256 + t;
        int x = j & 15, y = (j >> 4) & 15, z = j >> 8;
        bool val[7] = { true, x < 15, x > 0, y < 15, y > 0, z < 15, z < 14 };
        float wv[7];
        int r = 0;
        float M = -INFINITY;
        #pragma unroll
        for (int i = 0; i < 7; i++) {
            if (val[i]) { wv[i] = tw[j * 7 + r]; r++; M = fmaxf(M, wv[i]); }
            else wv[i] = 0.f;
        }
        float sum = 0.f;
        #pragma unroll
        for (int i = 0; i < 7; i++) if (val[i]) sum += __expf(wv[i] - M);
        g_amax[j] = -__logf(sum);
        #pragma unroll
        for (int i = 0; i < 7; i++)
            g_P7[i * SNUM + j] = val[i] ? __expf(wv[i] - M) : 0.f;
    } else {
        // ---- prior logsumexp (256 threads, 16 elems each) ----
        float v[16];
        float mx = -INFINITY;
        #pragma unroll
        for (int k = 0; k < 16; k++) { v[k] = pw[t + 256 * k]; mx = fmaxf(mx, v[k]); }
        __shared__ float red2[8];
        #pragma unroll
        for (int o = 16; o; o >>= 1) mx = fmaxf(mx, __shfl_xor_sync(0xffffffffu, mx, o));
        if ((t & 31) == 0) red2[t >> 5] = mx;
        __syncthreads();
        mx = red2[0];
        #pragma unroll
        for (int k = 1; k < 8; k++) mx = fmaxf(mx, red2[k]);
        float se = 0.f;
        #pragma unroll
        for (int k = 0; k < 16; k++) se += __expf(v[k] - mx);
        #pragma unroll
        for (int o = 16; o; o >>= 1) se += __shfl_xor_sync(0xffffffffu, se, o);
        __syncthreads();
        if ((t & 31) == 0) red2[t >> 5] = se;
        __syncthreads();
        if (t == 0) {
            float sum = 0.f;
            #pragma unroll
            for (int k = 0; k < 8; k++) sum += red2[k];
            g_plse[0] = mx + __logf(sum);
        }
    }
}

// ---------------- K2: 5-point (y,x) smoothing -> transposed log table ----------------
__global__ void k_smooth(const float* __restrict__ emis) {
    __shared__ float sm[256][33];        // padded: conflict-free both phases
    int v0 = blockIdx.x * 32;
    int z  = blockIdx.y;
    int t = threadIdx.x;                 // 256 threads
    int w = t >> 5, l = t & 31;
    int sbase = z * 256;
    #pragma unroll 4
    for (int rr = 0; rr < 32; rr++) {
        int r = w * 32 + rr;
        int s = sbase + r;
        float x = emis[(size_t)s * VNUM + v0 + l];
        sm[r][l] = __expf(x - g_lse[s]);
    }
    __syncthreads();
    int p = t;
    int x = p & 15, y = p >> 4;
    int pu = (y < 15) ? p + 16 : p;
    int pd = (y > 0)  ? p - 16 : p;
    int pl = (x < 15) ? p + 1  : p;
    int pr = (x > 0)  ? p - 1  : p;
    #pragma unroll 4
    for (int i = 0; i < 32; i++) {
        float Q = sm[p][i] + sm[pu][i] + sm[pd][i] + sm[pl][i] + sm[pr][i];
        g_LQT[(size_t)(v0 + i) * SNUM + sbase + p] = __logf(Q) - LOG5F;
    }
}

// ---------------- K3: token gather-sum -> all_emis (L,B,S) ----------------
__global__ void k_gather(const int* __restrict__ stories) {
    int b = blockIdx.x, l = blockIdx.y;
    __shared__ int tok[WNUM];
    if (threadIdx.x < WNUM) tok[threadIdx.x] = stories[(b * LNUM + l) * WNUM + threadIdx.x];
    __syncthreads();
    int t = threadIdx.x;                 // 256 threads, 16 states each
    float* dst = g_allemis + ((size_t)l * BNUM + b) * SNUM;
    #pragma unroll 4
    for (int i = 0; i < 16; i++) {
        int s = i * 256 + t;
        float acc = 0.f;
        #pragma unroll
        for (int w2 = 0; w2 < WNUM; w2++) {
            int tk = tok[w2];
            if (tk < VNUM) acc += g_LQT[(size_t)tk * SNUM + s];
        }
        dst[s] = acc;
    }
}

// ---------------- K5: forward recursion, one CTA per batch chain ----------------
__global__ void __launch_bounds__(512, 1)
k_forward(const float* __restrict__ pw, float* __restrict__ out) {
    __shared__ float sc[SNUM];
    __shared__ float sp[SNUM];
    __shared__ float red[16];
    int b = blockIdx.x;
    int t = threadIdx.x;                 // 512 threads, 8 states each (strided)
    int wid = t >> 5, lane = t & 31;

    // persistent per-thread transition rows (coalesced loads: [k][s] layout)
    float p7r[8][7], amr[8];
    #pragma unroll
    for (int st = 0; st < 8; st++) {
        int j = t + 512 * st;
        #pragma unroll
        for (int k = 0; k < 7; k++) p7r[st][k] = g_P7[k * SNUM + j];
        amr[st] = g_amax[j];
    }
    float plse = g_plse[0];

    // l = 0: score0 = all_emis[0] + log_softmax(prior)
    float lm = -INFINITY;
    #pragma unroll
    for (int st = 0; st < 8; st++) {
        int j = t + 512 * st;
        float v = g_allemis[(size_t)b * SNUM + j] + (pw[j] - plse);
        sc[j] = v;
        out[(size_t)b * SNUM + j] = v;
        lm = fmaxf(lm, v);
    }
    #pragma unroll
    for (int o = 16; o; o >>= 1) lm = fmaxf(lm, __shfl_xor_sync(0xffffffffu, lm, o));
    if (lane == 0) red[wid] = lm;
    __syncthreads();
    float m = red[0];
    #pragma unroll
    for (int k = 1; k < 16; k++) m = fmaxf(m, red[k]);

    for (int l = 1; l < LNUM; l++) {
        float emt[8];
        // phase A: sp = exp(score - m); prefetch this step's emissions
        #pragma unroll
        for (int st = 0; st < 8; st++) {
            int j = t + 512 * st;
            sp[j] = __expf(sc[j] - m);
            emt[st] = g_allemis[((size_t)l * BNUM + b) * SNUM + j];
        }
        __syncthreads();
        // phase B: 7-neighbor gather + log; invalid slots carry P7==0 so masked
        // addresses just wrap (&4095) — sp values are finite, 0*x == 0.
        float lm2 = -INFINITY;
        #pragma unroll
        for (int st = 0; st < 8; st++) {
            int j = t + 512 * st;
            float acc = p7r[st][0] * sp[j]
                      + p7r[st][1] * sp[(j + 1)   & (SNUM - 1)]
                      + p7r[st][2] * sp[(j - 1)   & (SNUM - 1)]
                      + p7r[st][3] * sp[(j + 16)  & (SNUM - 1)]
                      + p7r[st][4] * sp[(j - 16)  & (SNUM - 1)]
                      + p7r[st][5] * sp[(j + 256) & (SNUM - 1)]
                      + p7r[st][6] * sp[(j + 512) & (SNUM - 1)];
            float v = emt[st] + __logf(acc) + m + amr[st];
            sc[j] = v;
            out[((size_t)l * BNUM + b) * SNUM + j] = v;
            lm2 = fmaxf(lm2, v);
        }
        #pragma unroll
        for (int o = 16; o; o >>= 1) lm2 = fmaxf(lm2, __shfl_xor_sync(0xffffffffu, lm2, o));
        if (lane == 0) red[wid] = lm2;
        __syncthreads();
        m = red[0];
        #pragma unroll
        for (int k = 1; k < 16; k++) m = fmaxf(m, red[k]);
    }
}

// ---------------- launch ----------------
extern "C" void kernel_launch(void* const* d_in, const int* in_sizes, int n_in,
                              void* d_out, int out_size) {
    const int*   stories = nullptr;
    const float* trans_w = nullptr;
    const float* emis_w  = nullptr;
    const float* prior_w = nullptr;
    for (int i = 0; i < n_in; i++) {
        switch (in_sizes[i]) {
            case BNUM * LNUM * WNUM: stories = (const int*)d_in[i];   break; // 2048
            case SNUM * 7:           trans_w = (const float*)d_in[i]; break; // 28672
            case SNUM * VNUM:        emis_w  = (const float*)d_in[i]; break; // 8388608
            case SNUM:               prior_w = (const float*)d_in[i]; break; // 4096
            default: break; // story_length scalar
        }
    }
    float* out = (float*)d_out;

    k_prep<<<SNUM + 16 + 1, 256>>>(emis_w, trans_w, prior_w);
    k_smooth<<<dim3(VNUM / 32, ZDIM), 256>>>(emis_w);
    k_gather<<<dim3(BNUM, LNUM), 256>>>(stories);
    k_forward<<<BNUM, 512>>>(prior_w, out);
}

// round 3
// speedup vs baseline: 1.8132x; 1.1371x over previous
#include <cuda_runtime.h>
#include <cuda_bf16.h>
#include <math.h>

// Problem constants
#define XYDIM 16
#define ZDIM  16
#define SNUM  4096     // 16*16*16
#define VNUM  2048
#define BNUM  8
#define LNUM  32
#define WNUM  8

#define LOG5F 1.6094379124341003f

// ---------------- scratch (device globals: no allocation allowed) ----------------
__device__ float g_lse[SNUM];                      // row logsumexp of emis_w
__device__ float g_LQT[(size_t)VNUM * SNUM];       // smoothed log-emission, TRANSPOSED [v][s]  (32MB)
__device__ float g_allemis[LNUM * BNUM * SNUM];    // (L,B,S) emission sums (4MB)
__device__ float g_P7[7 * SNUM];                   // exp(logp - amax), fixed-offset slots, [k][s]
__device__ float g_amax[SNUM];
__device__ float g_plse[1];                        // prior logsumexp

// ---------------- K_prep: fused row-lse (4096 blocks) + trans (16) + prior (1) ----------------
__global__ void k_prep(const float* __restrict__ emis,
                       const float* __restrict__ tw,
                       const float* __restrict__ pw) {
    int bid = blockIdx.x;
    int t = threadIdx.x;                 // 256 threads

    if (bid < SNUM) {
        // ---- per-row logsumexp of emis_w ----
        int s = bid;
        const float4* row = reinterpret_cast<const float4*>(emis + (size_t)s * VNUM);
        float4 a = row[t];
        float4 b = row[t + 256];
        float mx = fmaxf(fmaxf(fmaxf(a.x, a.y), fmaxf(a.z, a.w)),
                         fmaxf(fmaxf(b.x, b.y), fmaxf(b.z, b.w)));
        __shared__ float red[8];
        #pragma unroll
        for (int o = 16; o; o >>= 1) mx = fmaxf(mx, __shfl_xor_sync(0xffffffffu, mx, o));
        if ((t & 31) == 0) red[t >> 5] = mx;
        __syncthreads();
        mx = red[0];
        #pragma unroll
        for (int k = 1; k < 8; k++) mx = fmaxf(mx, red[k]);
        float se = __expf(a.x - mx) + __expf(a.y - mx) + __expf(a.z - mx) + __expf(a.w - mx)
                 + __expf(b.x - mx) + __expf(b.y - mx) + __expf(b.z - mx) + __expf(b.w - mx);
        #pragma unroll
        for (int o = 16; o; o >>= 1) se += __shfl_xor_sync(0xffffffffu, se, o);
        __syncthreads();
        if ((t & 31) == 0) red[t >> 5] = se;
        __syncthreads();
        if (t == 0) {
            float sum = 0.f;
            #pragma unroll
            for (int k = 0; k < 8; k++) sum += red[k];
            g_lse[s] = mx + __logf(sum);
        }
    } else if (bid < SNUM + 16) {
        // ---- transition log-softmax with stable valid-first pairing ----
        int j = (bid - SNUM) * 256 + t;
        int x = j & 15, y = (j >> 4) & 15, z = j >> 8;
        bool val[7] = { true, x < 15, x > 0, y < 15, y > 0, z < 15, z < 14 };
        float wv[7];
        int r = 0;
        float M = -INFINITY;
        #pragma unroll
        for (int i = 0; i < 7; i++) {
            if (val[i]) { wv[i] = tw[j * 7 + r]; r++; M = fmaxf(M, wv[i]); }
            else wv[i] = 0.f;
        }
        float sum = 0.f;
        #pragma unroll
        for (int i = 0; i < 7; i++) if (val[i]) sum += __expf(wv[i] - M);
        g_amax[j] = -__logf(sum);
        #pragma unroll
        for (int i = 0; i < 7; i++)
            g_P7[i * SNUM + j] = val[i] ? __expf(wv[i] - M) : 0.f;
    } else {
        // ---- prior logsumexp ----
        float v[16];
        float mx = -INFINITY;
        #pragma unroll
        for (int k = 0; k < 16; k++) { v[k] = pw[t + 256 * k]; mx = fmaxf(mx, v[k]); }
        __shared__ float red2[8];
        #pragma unroll
        for (int o = 16; o; o >>= 1) mx = fmaxf(mx, __shfl_xor_sync(0xffffffffu, mx, o));
        if ((t & 31) == 0) red2[t >> 5] = mx;
        __syncthreads();
        mx = red2[0];
        #pragma unroll
        for (int k = 1; k < 8; k++) mx = fmaxf(mx, red2[k]);
        float se = 0.f;
        #pragma unroll
        for (int k = 0; k < 16; k++) se += __expf(v[k] - mx);
        #pragma unroll
        for (int o = 16; o; o >>= 1) se += __shfl_xor_sync(0xffffffffu, se, o);
        __syncthreads();
        if ((t & 31) == 0) red2[t >> 5] = se;
        __syncthreads();
        if (t == 0) {
            float sum = 0.f;
            #pragma unroll
            for (int k = 0; k < 8; k++) sum += red2[k];
            g_plse[0] = mx + __logf(sum);
        }
    }
}

// ---------------- K2: 5-point (y,x) smoothing -> transposed log table ----------------
__global__ void k_smooth(const float* __restrict__ emis) {
    __shared__ float sm[256][33];        // padded: conflict-free both phases
    int v0 = blockIdx.x * 32;
    int z  = blockIdx.y;
    int t = threadIdx.x;                 // 256 threads
    int w = t >> 5, l = t & 31;
    int sbase = z * 256;
    #pragma unroll 4
    for (int rr = 0; rr < 32; rr++) {
        int r = w * 32 + rr;
        int s = sbase + r;
        float x = emis[(size_t)s * VNUM + v0 + l];
        sm[r][l] = __expf(x - g_lse[s]);
    }
    __syncthreads();
    int p = t;
    int x = p & 15, y = p >> 4;
    int pu = (y < 15) ? p + 16 : p;
    int pd = (y > 0)  ? p - 16 : p;
    int pl = (x < 15) ? p + 1  : p;
    int pr = (x > 0)  ? p - 1  : p;
    #pragma unroll 4
    for (int i = 0; i < 32; i++) {
        float Q = sm[p][i] + sm[pu][i] + sm[pd][i] + sm[pl][i] + sm[pr][i];
        g_LQT[(size_t)(v0 + i) * SNUM + sbase + p] = __logf(Q) - LOG5F;
    }
}

// ---------------- K3: token gather-sum -> all_emis (L,B,S), float4 ----------------
__global__ void k_gather(const int* __restrict__ stories) {
    int b = blockIdx.x, l = blockIdx.y;
    __shared__ int tok[WNUM];
    if (threadIdx.x < WNUM) tok[threadIdx.x] = stories[(b * LNUM + l) * WNUM + threadIdx.x];
    __syncthreads();
    int t = threadIdx.x;                 // 256 threads, 4 float4s each
    float4* dst = reinterpret_cast<float4*>(g_allemis + ((size_t)l * BNUM + b) * SNUM);
    float4 acc[4];
    #pragma unroll
    for (int i = 0; i < 4; i++) acc[i] = make_float4(0.f, 0.f, 0.f, 0.f);
    #pragma unroll
    for (int w2 = 0; w2 < WNUM; w2++) {
        int tk = tok[w2];
        if (tk < VNUM) {
            const float4* row = reinterpret_cast<const float4*>(g_LQT + (size_t)tk * SNUM);
            #pragma unroll
            for (int i = 0; i < 4; i++) {
                float4 r = row[t + 256 * i];
                acc[i].x += r.x; acc[i].y += r.y; acc[i].z += r.z; acc[i].w += r.w;
            }
        }
    }
    #pragma unroll
    for (int i = 0; i < 4; i++) dst[t + 256 * i] = acc[i];
}

// ---------------- K5: forward recursion — contiguous 8 states/thread, vectorized ----------------
// Neighbor offsets {0,+1,-1,+16,-16,+256,+512}. ±1 handled in registers/shfl
// (edge lanes land on x=0/15 faces where P7==0, so clamped shfl garbage is
// annihilated). ±16/+256/+512 via LDS.128 from a zero-padded sp buffer.
__global__ void __launch_bounds__(512, 1)
k_forward(const float* __restrict__ pw, float* __restrict__ out) {
    __shared__ float sp[16 + SNUM + 512];     // [halo16 | 4096 | halo512]
    __shared__ float red[16];
    __shared__ float mshare;
    int b = blockIdx.x;
    int t = threadIdx.x;                 // 512 threads, 8 contiguous states each
    int wid = t >> 5, lane = t & 31;
    int j0 = t * 8;

    // persistent transition rows (coalesced float4 loads, [k][s] layout)
    float p7r[7][8], am[8];
    #pragma unroll
    for (int k = 0; k < 7; k++) {
        float4 a = *reinterpret_cast<const float4*>(&g_P7[k * SNUM + j0]);
        float4 c = *reinterpret_cast<const float4*>(&g_P7[k * SNUM + j0 + 4]);
        p7r[k][0] = a.x; p7r[k][1] = a.y; p7r[k][2] = a.z; p7r[k][3] = a.w;
        p7r[k][4] = c.x; p7r[k][5] = c.y; p7r[k][6] = c.z; p7r[k][7] = c.w;
    }
    {
        float4 a = *reinterpret_cast<const float4*>(&g_amax[j0]);
        float4 c = *reinterpret_cast<const float4*>(&g_amax[j0 + 4]);
        am[0] = a.x; am[1] = a.y; am[2] = a.z; am[3] = a.w;
        am[4] = c.x; am[5] = c.y; am[6] = c.z; am[7] = c.w;
    }
    float plse = g_plse[0];

    // zero halos once (never overwritten; P7==0 masks any read of them)
    if (t < 16)  sp[t] = 0.f;
    if (t < 512) sp[16 + SNUM + t] = 0.f;

    // l = 0: score0 = all_emis[0] + log_softmax(prior)
    float v[8];
    {
        float4 e0 = *reinterpret_cast<const float4*>(&g_allemis[(size_t)b * SNUM + j0]);
        float4 e1 = *reinterpret_cast<const float4*>(&g_allemis[(size_t)b * SNUM + j0 + 4]);
        float4 q0 = *reinterpret_cast<const float4*>(&pw[j0]);
        float4 q1 = *reinterpret_cast<const float4*>(&pw[j0 + 4]);
        v[0] = e0.x + q0.x - plse; v[1] = e0.y + q0.y - plse;
        v[2] = e0.z + q0.z - plse; v[3] = e0.w + q0.w - plse;
        v[4] = e1.x + q1.x - plse; v[5] = e1.y + q1.y - plse;
        v[6] = e1.z + q1.z - plse; v[7] = e1.w + q1.w - plse;
        *reinterpret_cast<float4*>(&out[(size_t)b * SNUM + j0])     = make_float4(v[0], v[1], v[2], v[3]);
        *reinterpret_cast<float4*>(&out[(size_t)b * SNUM + j0 + 4]) = make_float4(v[4], v[5], v[6], v[7]);
    }
    float lm = v[0];
    #pragma unroll
    for (int st = 1; st < 8; st++) lm = fmaxf(lm, v[st]);
    #pragma unroll
    for (int o = 16; o; o >>= 1) lm = fmaxf(lm, __shfl_xor_sync(0xffffffffu, lm, o));
    if (lane == 0) red[wid] = lm;
    __syncthreads();
    if (t < 16) {
        float x = red[t];
        #pragma unroll
        for (int o = 8; o; o >>= 1) x = fmaxf(x, __shfl_xor_sync(0xffffu, x, o));
        if (t == 0) mshare = x;
    }
    __syncthreads();
    float m = mshare;

    for (int l = 1; l < LNUM; l++) {
        // phase A: sp = exp(score - m) from registers; prefetch emissions
        float s[8];
        #pragma unroll
        for (int st = 0; st < 8; st++) s[st] = __expf(v[st] - m);
        *reinterpret_cast<float4*>(&sp[16 + j0])     = make_float4(s[0], s[1], s[2], s[3]);
        *reinterpret_cast<float4*>(&sp[16 + j0 + 4]) = make_float4(s[4], s[5], s[6], s[7]);
        float em[8];
        {
            const float* ep = g_allemis + ((size_t)l * BNUM + b) * SNUM + j0;
            float4 e0 = *reinterpret_cast<const float4*>(ep);
            float4 e1 = *reinterpret_cast<const float4*>(ep + 4);
            em[0] = e0.x; em[1] = e0.y; em[2] = e0.z; em[3] = e0.w;
            em[4] = e1.x; em[5] = e1.y; em[6] = e1.z; em[7] = e1.w;
        }
        // cross-thread ±1 values (register exchange; edges masked by P7==0)
        float rgt = __shfl_down_sync(0xffffffffu, s[0], 1);  // next thread's s[0]
        float lft = __shfl_up_sync(0xffffffffu, s[7], 1);    // prev thread's s[7]
        __syncthreads();

        // phase B: vector loads of the three smem-resident offsets
        float n16[8], m16[8], n256[8], n512[8];
        {
            float4 a, c;
            a = *reinterpret_cast<const float4*>(&sp[16 + j0 + 16]);
            c = *reinterpret_cast<const float4*>(&sp[16 + j0 + 20]);
            n16[0]=a.x; n16[1]=a.y; n16[2]=a.z; n16[3]=a.w; n16[4]=c.x; n16[5]=c.y; n16[6]=c.z; n16[7]=c.w;
            a = *reinterpret_cast<const float4*>(&sp[16 + j0 - 16]);
            c = *reinterpret_cast<const float4*>(&sp[16 + j0 - 12]);
            m16[0]=a.x; m16[1]=a.y; m16[2]=a.z; m16[3]=a.w; m16[4]=c.x; m16[5]=c.y; m16[6]=c.z; m16[7]=c.w;
            a = *reinterpret_cast<const float4*>(&sp[16 + j0 + 256]);
            c = *reinterpret_cast<const float4*>(&sp[16 + j0 + 260]);
            n256[0]=a.x; n256[1]=a.y; n256[2]=a.z; n256[3]=a.w; n256[4]=c.x; n256[5]=c.y; n256[6]=c.z; n256[7]=c.w;
            a = *reinterpret_cast<const float4*>(&sp[16 + j0 + 512]);
            c = *reinterpret_cast<const float4*>(&sp[16 + j0 + 516]);
            n512[0]=a.x; n512[1]=a.y; n512[2]=a.z; n512[3]=a.w; n512[4]=c.x; n512[5]=c.y; n512[6]=c.z; n512[7]=c.w;
        }
        float lm2 = -INFINITY;
        #pragma unroll
        for (int st = 0; st < 8; st++) {
            float rn = (st < 7) ? s[st + 1] : rgt;
            float ln = (st > 0) ? s[st - 1] : lft;
            float acc = p7r[0][st] * s[st]
                      + p7r[1][st] * rn
                      + p7r[2][st] * ln
                      + p7r[3][st] * n16[st]
                      + p7r[4][st] * m16[st]
                      + p7r[5][st] * n256[st]
                      + p7r[6][st] * n512[st];
            v[st] = em[st] + __logf(acc) + m + am[st];
            lm2 = fmaxf(lm2, v[st]);
        }
        {
            float* op = out + ((size_t)l * BNUM + b) * SNUM + j0;
            *reinterpret_cast<float4*>(op)     = make_float4(v[0], v[1], v[2], v[3]);
            *reinterpret_cast<float4*>(op + 4) = make_float4(v[4], v[5], v[6], v[7]);
        }
        #pragma unroll
        for (int o = 16; o; o >>= 1) lm2 = fmaxf(lm2, __shfl_xor_sync(0xffffffffu, lm2, o));
        if (lane == 0) red[wid] = lm2;
        __syncthreads();
        if (t < 16) {
            float x = red[t];
            #pragma unroll
            for (int o = 8; o; o >>= 1) x = fmaxf(x, __shfl_xor_sync(0xffffu, x, o));
            if (t == 0) mshare = x;
        }
        __syncthreads();
        m = mshare;
    }
}

// ---------------- launch ----------------
extern "C" void kernel_launch(void* const* d_in, const int* in_sizes, int n_in,
                              void* d_out, int out_size) {
    const int*   stories = nullptr;
    const float* trans_w = nullptr;
    const float* emis_w  = nullptr;
    const float* prior_w = nullptr;
    for (int i = 0; i < n_in; i++) {
        switch (in_sizes[i]) {
            case BNUM * LNUM * WNUM: stories = (const int*)d_in[i];   break; // 2048
            case SNUM * 7:           trans_w = (const float*)d_in[i]; break; // 28672
            case SNUM * VNUM:        emis_w  = (const float*)d_in[i]; break; // 8388608
            case SNUM:               prior_w = (const float*)d_in[i]; break; // 4096
            default: break; // story_length scalar
        }
    }
    float* out = (float*)d_out;

    k_prep<<<SNUM + 16 + 1, 256>>>(emis_w, trans_w, prior_w);
    k_smooth<<<dim3(VNUM / 32, ZDIM), 256>>>(emis_w);
    k_gather<<<dim3(BNUM, LNUM), 256>>>(stories);
    k_forward<<<BNUM, 512>>>(prior_w, out);
}

// round 5
// speedup vs baseline: 1.9885x; 1.0967x over previous
#include <cuda_runtime.h>
#include <cuda_bf16.h>
#include <math.h>

// Problem constants
#define XYDIM 16
#define ZDIM  16
#define SNUM  4096     // 16*16*16
#define VNUM  2048
#define BNUM  8
#define LNUM  32
#define WNUM  8

#define LOG5F 1.6094379124341003f

// ---------------- scratch (device globals: no allocation allowed) ----------------
__device__ float g_lse[SNUM];                      // row logsumexp of emis_w
__device__ float g_LQT[(size_t)VNUM * SNUM];       // smoothed log-emission, TRANSPOSED [v][s]  (32MB)
__device__ float g_allemis[LNUM * BNUM * SNUM];    // (L,B,S) emission sums (4MB)
__device__ float g_P7[7 * SNUM];                   // exp(logp - amax), fixed-offset slots, [k][s]
__device__ float g_amax[SNUM];
__device__ float g_plse[1];                        // prior logsumexp

// ---------------- K_prep: fused row-lse (4096 blocks) + trans (16) + prior (1) ----------------
__global__ void k_prep(const float* __restrict__ emis,
                       const float* __restrict__ tw,
                       const float* __restrict__ pw) {
    int bid = blockIdx.x;
    int t = threadIdx.x;                 // 256 threads

    if (bid < SNUM) {
        // ---- per-row logsumexp of emis_w ----
        int s = bid;
        const float4* row = reinterpret_cast<const float4*>(emis + (size_t)s * VNUM);
        float4 a = row[t];
        float4 b = row[t + 256];
        float mx = fmaxf(fmaxf(fmaxf(a.x, a.y), fmaxf(a.z, a.w)),
                         fmaxf(fmaxf(b.x, b.y), fmaxf(b.z, b.w)));
        __shared__ float red[8];
        #pragma unroll
        for (int o = 16; o; o >>= 1) mx = fmaxf(mx, __shfl_xor_sync(0xffffffffu, mx, o));
        if ((t & 31) == 0) red[t >> 5] = mx;
        __syncthreads();
        mx = red[0];
        #pragma unroll
        for (int k = 1; k < 8; k++) mx = fmaxf(mx, red[k]);
        float se = __expf(a.x - mx) + __expf(a.y - mx) + __expf(a.z - mx) + __expf(a.w - mx)
                 + __expf(b.x - mx) + __expf(b.y - mx) + __expf(b.z - mx) + __expf(b.w - mx);
        #pragma unroll
        for (int o = 16; o; o >>= 1) se += __shfl_xor_sync(0xffffffffu, se, o);
        __syncthreads();
        if ((t & 31) == 0) red[t >> 5] = se;
        __syncthreads();
        if (t == 0) {
            float sum = 0.f;
            #pragma unroll
            for (int k = 0; k < 8; k++) sum += red[k];
            g_lse[s] = mx + __logf(sum);
        }
    } else if (bid < SNUM + 16) {
        // ---- transition log-softmax with stable valid-first pairing ----
        int j = (bid - SNUM) * 256 + t;
        int x = j & 15, y = (j >> 4) & 15, z = j >> 8;
        bool val[7] = { true, x < 15, x > 0, y < 15, y > 0, z < 15, z < 14 };
        float wv[7];
        int r = 0;
        float M = -INFINITY;
        #pragma unroll
        for (int i = 0; i < 7; i++) {
            if (val[i]) { wv[i] = tw[j * 7 + r]; r++; M = fmaxf(M, wv[i]); }
            else wv[i] = 0.f;
        }
        float sum = 0.f;
        #pragma unroll
        for (int i = 0; i < 7; i++) if (val[i]) sum += __expf(wv[i] - M);
        g_amax[j] = -__logf(sum);
        #pragma unroll
        for (int i = 0; i < 7; i++)
            g_P7[i * SNUM + j] = val[i] ? __expf(wv[i] - M) : 0.f;
    } else {
        // ---- prior logsumexp ----
        float v[16];
        float mx = -INFINITY;
        #pragma unroll
        for (int k = 0; k < 16; k++) { v[k] = pw[t + 256 * k]; mx = fmaxf(mx, v[k]); }
        __shared__ float red2[8];
        #pragma unroll
        for (int o = 16; o; o >>= 1) mx = fmaxf(mx, __shfl_xor_sync(0xffffffffu, mx, o));
        if ((t & 31) == 0) red2[t >> 5] = mx;
        __syncthreads();
        mx = red2[0];
        #pragma unroll
        for (int k = 1; k < 8; k++) mx = fmaxf(mx, red2[k]);
        float se = 0.f;
        #pragma unroll
        for (int k = 0; k < 16; k++) se += __expf(v[k] - mx);
        #pragma unroll
        for (int o = 16; o; o >>= 1) se += __shfl_xor_sync(0xffffffffu, se, o);
        __syncthreads();
        if ((t & 31) == 0) red2[t >> 5] = se;
        __syncthreads();
        if (t == 0) {
            float sum = 0.f;
            #pragma unroll
            for (int k = 0; k < 8; k++) sum += red2[k];
            g_plse[0] = mx + __logf(sum);
        }
    }
}

// ---------------- K2: 5-point (y,x) smoothing -> transposed log table ----------------
__global__ void k_smooth(const float* __restrict__ emis) {
    __shared__ float sm[256][33];        // padded: conflict-free both phases
    int v0 = blockIdx.x * 32;
    int z  = blockIdx.y;
    int t = threadIdx.x;                 // 256 threads
    int w = t >> 5, l = t & 31;
    int sbase = z * 256;
    #pragma unroll 4
    for (int rr = 0; rr < 32; rr++) {
        int r = w * 32 + rr;
        int s = sbase + r;
        float x = emis[(size_t)s * VNUM + v0 + l];
        sm[r][l] = __expf(x - g_lse[s]);
    }
    __syncthreads();
    int p = t;
    int x = p & 15, y = p >> 4;
    int pu = (y < 15) ? p + 16 : p;
    int pd = (y > 0)  ? p - 16 : p;
    int pl = (x < 15) ? p + 1  : p;
    int pr = (x > 0)  ? p - 1  : p;
    #pragma unroll 4
    for (int i = 0; i < 32; i++) {
        float Q = sm[p][i] + sm[pu][i] + sm[pd][i] + sm[pl][i] + sm[pr][i];
        g_LQT[(size_t)(v0 + i) * SNUM + sbase + p] = __logf(Q) - LOG5F;
    }
}

// ---------------- K3: token gather-sum -> all_emis (L,B,S), float4 ----------------
__global__ void k_gather(const int* __restrict__ stories) {
    int b = blockIdx.x, l = blockIdx.y;
    __shared__ int tok[WNUM];
    if (threadIdx.x < WNUM) tok[threadIdx.x] = stories[(b * LNUM + l) * WNUM + threadIdx.x];
    __syncthreads();
    int t = threadIdx.x;                 // 256 threads, 4 float4s each
    float4* dst = reinterpret_cast<float4*>(g_allemis + ((size_t)l * BNUM + b) * SNUM);
    float4 acc[4];
    #pragma unroll
    for (int i = 0; i < 4; i++) acc[i] = make_float4(0.f, 0.f, 0.f, 0.f);
    #pragma unroll
    for (int w2 = 0; w2 < WNUM; w2++) {
        int tk = tok[w2];
        if (tk < VNUM) {
            const float4* row = reinterpret_cast<const float4*>(g_LQT + (size_t)tk * SNUM);
            #pragma unroll
            for (int i = 0; i < 4; i++) {
                float4 r = row[t + 256 * i];
                acc[i].x += r.x; acc[i].y += r.y; acc[i].z += r.z; acc[i].w += r.w;
            }
        }
    }
    #pragma unroll
    for (int i = 0; i < 4; i++) dst[t + 256 * i] = acc[i];
}

// ---------------- K5: forward recursion — 2 barriers/step, shfl neighbors ----------------
// Offsets {0,+1,-1,+16,-16,+256,+512}. ±1 = intra-thread regs + shfl by 1;
// ±16 = shfl by 2 (warp-edge lanes land on y=0/y=15 faces where P7==0, so
// clamped-shuffle garbage is annihilated). Only +256/+512 go through smem
// (zero back-halo; z>=14/15 faces masked by P7==0).
// Block max: warp maxes -> red[16] at tail of compute phase; every thread
// reduces red itself next step (exact same-step max, as the reference).
__global__ void __launch_bounds__(512, 1)
k_forward(const float* __restrict__ pw, float* __restrict__ out) {
    __shared__ float sp[SNUM + 512];     // [4096 | halo512]
    __shared__ float red[16];
    int b = blockIdx.x;
    int t = threadIdx.x;                 // 512 threads, 8 contiguous states each
    int wid = t >> 5, lane = t & 31;
    int j0 = t * 8;

    // persistent transition rows (coalesced float4 loads, [k][s] layout)
    float p7r[7][8], am[8];
    #pragma unroll
    for (int k = 0; k < 7; k++) {
        float4 a = *reinterpret_cast<const float4*>(&g_P7[k * SNUM + j0]);
        float4 c = *reinterpret_cast<const float4*>(&g_P7[k * SNUM + j0 + 4]);
        p7r[k][0] = a.x; p7r[k][1] = a.y; p7r[k][2] = a.z; p7r[k][3] = a.w;
        p7r[k][4] = c.x; p7r[k][5] = c.y; p7r[k][6] = c.z; p7r[k][7] = c.w;
    }
    {
        float4 a = *reinterpret_cast<const float4*>(&g_amax[j0]);
        float4 c = *reinterpret_cast<const float4*>(&g_amax[j0 + 4]);
        am[0] = a.x; am[1] = a.y; am[2] = a.z; am[3] = a.w;
        am[4] = c.x; am[5] = c.y; am[6] = c.z; am[7] = c.w;
    }
    float plse = g_plse[0];

    // zero back halo once (never overwritten; P7==0 masks any read of it)
    sp[SNUM + t] = 0.f;

    // l = 0: score0 = all_emis[0] + log_softmax(prior)
    float v[8];
    {
        float4 e0 = *reinterpret_cast<const float4*>(&g_allemis[(size_t)b * SNUM + j0]);
        float4 e1 = *reinterpret_cast<const float4*>(&g_allemis[(size_t)b * SNUM + j0 + 4]);
        float4 q0 = *reinterpret_cast<const float4*>(&pw[j0]);
        float4 q1 = *reinterpret_cast<const float4*>(&pw[j0 + 4]);
        v[0] = e0.x + q0.x - plse; v[1] = e0.y + q0.y - plse;
        v[2] = e0.z + q0.z - plse; v[3] = e0.w + q0.w - plse;
        v[4] = e1.x + q1.x - plse; v[5] = e1.y + q1.y - plse;
        v[6] = e1.z + q1.z - plse; v[7] = e1.w + q1.w - plse;
        *reinterpret_cast<float4*>(&out[(size_t)b * SNUM + j0])     = make_float4(v[0], v[1], v[2], v[3]);
        *reinterpret_cast<float4*>(&out[(size_t)b * SNUM + j0 + 4]) = make_float4(v[4], v[5], v[6], v[7]);
    }
    {
        float lm = v[0];
        #pragma unroll
        for (int st = 1; st < 8; st++) lm = fmaxf(lm, v[st]);
        #pragma unroll
        for (int o = 16; o; o >>= 1) lm = fmaxf(lm, __shfl_xor_sync(0xffffffffu, lm, o));
        if (lane == 0) red[wid] = lm;
    }

    for (int l = 1; l < LNUM; l++) {
        __syncthreads();                 // red[] published; prev sp reads retired
        float m;
        {
            float4 r0 = *reinterpret_cast<const float4*>(&red[0]);
            float4 r1 = *reinterpret_cast<const float4*>(&red[4]);
            float4 r2 = *reinterpret_cast<const float4*>(&red[8]);
            float4 r3 = *reinterpret_cast<const float4*>(&red[12]);
            float m0 = fmaxf(fmaxf(r0.x, r0.y), fmaxf(r0.z, r0.w));
            float m1 = fmaxf(fmaxf(r1.x, r1.y), fmaxf(r1.z, r1.w));
            float m2 = fmaxf(fmaxf(r2.x, r2.y), fmaxf(r2.z, r2.w));
            float m3 = fmaxf(fmaxf(r3.x, r3.y), fmaxf(r3.z, r3.w));
            m = fmaxf(fmaxf(m0, m1), fmaxf(m2, m3));
        }
        // phase A: sp = exp(score - m); publish; prefetch emissions; ±1 shfl
        float s[8];
        #pragma unroll
        for (int st = 0; st < 8; st++) s[st] = __expf(v[st] - m);
        *reinterpret_cast<float4*>(&sp[j0])     = make_float4(s[0], s[1], s[2], s[3]);
        *reinterpret_cast<float4*>(&sp[j0 + 4]) = make_float4(s[4], s[5], s[6], s[7]);
        float em[8];
        {
            const float* ep = g_allemis + ((size_t)l * BNUM + b) * SNUM + j0;
            float4 e0 = *reinterpret_cast<const float4*>(ep);
            float4 e1 = *reinterpret_cast<const float4*>(ep + 4);
            em[0] = e0.x; em[1] = e0.y; em[2] = e0.z; em[3] = e0.w;
            em[4] = e1.x; em[5] = e1.y; em[6] = e1.z; em[7] = e1.w;
        }
        float rgt = __shfl_down_sync(0xffffffffu, s[0], 1);  // +1 across thread edge
        float lft = __shfl_up_sync(0xffffffffu, s[7], 1);    // -1 across thread edge
        __syncthreads();                 // sp ready

        // phase B: +256/+512 from smem, ±16 via shfl-by-2, compute, publish max
        float n256[8], n512[8];
        {
            float4 a, c;
            a = *reinterpret_cast<const float4*>(&sp[j0 + 256]);
            c = *reinterpret_cast<const float4*>(&sp[j0 + 260]);
            n256[0]=a.x; n256[1]=a.y; n256[2]=a.z; n256[3]=a.w;
            n256[4]=c.x; n256[5]=c.y; n256[6]=c.z; n256[7]=c.w;
            a = *reinterpret_cast<const float4*>(&sp[j0 + 512]);
            c = *reinterpret_cast<const float4*>(&sp[j0 + 516]);
            n512[0]=a.x; n512[1]=a.y; n512[2]=a.z; n512[3]=a.w;
            n512[4]=c.x; n512[5]=c.y; n512[6]=c.z; n512[7]=c.w;
        }
        float lm = -INFINITY;
        #pragma unroll
        for (int st = 0; st < 8; st++) {
            float u = __shfl_down_sync(0xffffffffu, s[st], 2);   // +16 (y+1)
            float d = __shfl_up_sync(0xffffffffu, s[st], 2);     // -16 (y-1)
            float rn = (st < 7) ? s[st + 1] : rgt;
            float ln = (st > 0) ? s[st - 1] : lft;
            float acc = p7r[0][st] * s[st]
                      + p7r[1][st] * rn
                      + p7r[2][st] * ln
                      + p7r[3][st] * u
                      + p7r[4][st] * d
                      + p7r[5][st] * n256[st]
                      + p7r[6][st] * n512[st];
            v[st] = em[st] + __logf(acc) + m + am[st];
            lm = fmaxf(lm, v[st]);
        }
        {
            float* op = out + ((size_t)l * BNUM + b) * SNUM + j0;
            *reinterpret_cast<float4*>(op)     = make_float4(v[0], v[1], v[2], v[3]);
            *reinterpret_cast<float4*>(op + 4) = make_float4(v[4], v[5], v[6], v[7]);
        }
        #pragma unroll
        for (int o = 16; o; o >>= 1) lm = fmaxf(lm, __shfl_xor_sync(0xffffffffu, lm, o));
        if (lane == 0) red[wid] = lm;
    }
}

// ---------------- launch ----------------
extern "C" void kernel_launch(void* const* d_in, const int* in_sizes, int n_in,
                              void* d_out, int out_size) {
    const int*   stories = nullptr;
    const float* trans_w = nullptr;
    const float* emis_w  = nullptr;
    const float* prior_w = nullptr;
    for (int i = 0; i < n_in; i++) {
        switch (in_sizes[i]) {
            case BNUM * LNUM * WNUM: stories = (const int*)d_in[i];   break; // 2048
            case SNUM * 7:           trans_w = (const float*)d_in[i]; break; // 28672
            case SNUM * VNUM:        emis_w  = (const float*)d_in[i]; break; // 8388608
            case SNUM:               prior_w = (const float*)d_in[i]; break; // 4096
            default: break; // story_length scalar
        }
    }
    float* out = (float*)d_out;

    k_prep<<<SNUM + 16 + 1, 256>>>(emis_w, trans_w, prior_w);
    k_smooth<<<dim3(VNUM / 32, ZDIM), 256>>>(emis_w);
    k_gather<<<dim3(BNUM, LNUM), 256>>>(stories);
    k_forward<<<BNUM, 512>>>(prior_w, out);
}

// round 6
// speedup vs baseline: 2.1831x; 1.0979x over previous
#include <cuda_runtime.h>
#include <cuda_bf16.h>
#include <math.h>

// Problem constants
#define XYDIM 16
#define ZDIM  16
#define SNUM  4096     // 16*16*16
#define VNUM  2048
#define BNUM  8
#define LNUM  32
#define WNUM  8

#define LOG5F 1.6094379124341003f

// ---------------- scratch (device globals: no allocation allowed) ----------------
__device__ float g_lse[SNUM];                      // row logsumexp of emis_w
__device__ float g_LQT[(size_t)VNUM * SNUM];       // smoothed log-emission, TRANSPOSED [v][s]  (32MB)
__device__ float g_allemis[LNUM * BNUM * SNUM];    // (L,B,S) emission sums + folded prior/amax
__device__ float g_P7[7 * SNUM];                   // exp(logp - amax), fixed-offset slots, [k][s]
__device__ float g_amax[SNUM];
__device__ float g_plse[1];                        // prior logsumexp

// ---------------- K_prep: fused row-lse (4096 blocks) + trans (16) + prior (1) ----------------
__global__ void k_prep(const float* __restrict__ emis,
                       const float* __restrict__ tw,
                       const float* __restrict__ pw) {
    int bid = blockIdx.x;
    int t = threadIdx.x;                 // 256 threads

    if (bid < SNUM) {
        // ---- per-row logsumexp of emis_w ----
        int s = bid;
        const float4* row = reinterpret_cast<const float4*>(emis + (size_t)s * VNUM);
        float4 a = row[t];
        float4 b = row[t + 256];
        float mx = fmaxf(fmaxf(fmaxf(a.x, a.y), fmaxf(a.z, a.w)),
                         fmaxf(fmaxf(b.x, b.y), fmaxf(b.z, b.w)));
        __shared__ float red[8];
        #pragma unroll
        for (int o = 16; o; o >>= 1) mx = fmaxf(mx, __shfl_xor_sync(0xffffffffu, mx, o));
        if ((t & 31) == 0) red[t >> 5] = mx;
        __syncthreads();
        mx = red[0];
        #pragma unroll
        for (int k = 1; k < 8; k++) mx = fmaxf(mx, red[k]);
        float se = __expf(a.x - mx) + __expf(a.y - mx) + __expf(a.z - mx) + __expf(a.w - mx)
                 + __expf(b.x - mx) + __expf(b.y - mx) + __expf(b.z - mx) + __expf(b.w - mx);
        #pragma unroll
        for (int o = 16; o; o >>= 1) se += __shfl_xor_sync(0xffffffffu, se, o);
        __syncthreads();
        if ((t & 31) == 0) red[t >> 5] = se;
        __syncthreads();
        if (t == 0) {
            float sum = 0.f;
            #pragma unroll
            for (int k = 0; k < 8; k++) sum += red[k];
            g_lse[s] = mx + __logf(sum);
        }
    } else if (bid < SNUM + 16) {
        // ---- transition log-softmax with stable valid-first pairing ----
        int j = (bid - SNUM) * 256 + t;
        int x = j & 15, y = (j >> 4) & 15, z = j >> 8;
        bool val[7] = { true, x < 15, x > 0, y < 15, y > 0, z < 15, z < 14 };
        float wv[7];
        int r = 0;
        float M = -INFINITY;
        #pragma unroll
        for (int i = 0; i < 7; i++) {
            if (val[i]) { wv[i] = tw[j * 7 + r]; r++; M = fmaxf(M, wv[i]); }
            else wv[i] = 0.f;
        }
        float sum = 0.f;
        #pragma unroll
        for (int i = 0; i < 7; i++) if (val[i]) sum += __expf(wv[i] - M);
        g_amax[j] = -__logf(sum);
        #pragma unroll
        for (int i = 0; i < 7; i++)
            g_P7[i * SNUM + j] = val[i] ? __expf(wv[i] - M) : 0.f;
    } else {
        // ---- prior logsumexp ----
        float v[16];
        float mx = -INFINITY;
        #pragma unroll
        for (int k = 0; k < 16; k++) { v[k] = pw[t + 256 * k]; mx = fmaxf(mx, v[k]); }
        __shared__ float red2[8];
        #pragma unroll
        for (int o = 16; o; o >>= 1) mx = fmaxf(mx, __shfl_xor_sync(0xffffffffu, mx, o));
        if ((t & 31) == 0) red2[t >> 5] = mx;
        __syncthreads();
        mx = red2[0];
        #pragma unroll
        for (int k = 1; k < 8; k++) mx = fmaxf(mx, red2[k]);
        float se = 0.f;
        #pragma unroll
        for (int k = 0; k < 16; k++) se += __expf(v[k] - mx);
        #pragma unroll
        for (int o = 16; o; o >>= 1) se += __shfl_xor_sync(0xffffffffu, se, o);
        __syncthreads();
        if ((t & 31) == 0) red2[t >> 5] = se;
        __syncthreads();
        if (t == 0) {
            float sum = 0.f;
            #pragma unroll
            for (int k = 0; k < 8; k++) sum += red2[k];
            g_plse[0] = mx + __logf(sum);
        }
    }
}

// ---------------- K2: 5-point (y,x) smoothing -> transposed log table ----------------
__global__ void k_smooth(const float* __restrict__ emis) {
    __shared__ float sm[256][33];        // padded: conflict-free both phases
    int v0 = blockIdx.x * 32;
    int z  = blockIdx.y;
    int t = threadIdx.x;                 // 256 threads
    int w = t >> 5, l = t & 31;
    int sbase = z * 256;
    #pragma unroll 4
    for (int rr = 0; rr < 32; rr++) {
        int r = w * 32 + rr;
        int s = sbase + r;
        float x = emis[(size_t)s * VNUM + v0 + l];
        sm[r][l] = __expf(x - g_lse[s]);
    }
    __syncthreads();
    int p = t;
    int x = p & 15, y = p >> 4;
    int pu = (y < 15) ? p + 16 : p;
    int pd = (y > 0)  ? p - 16 : p;
    int pl = (x < 15) ? p + 1  : p;
    int pr = (x > 0)  ? p - 1  : p;
    #pragma unroll 4
    for (int i = 0; i < 32; i++) {
        float Q = sm[p][i] + sm[pu][i] + sm[pd][i] + sm[pl][i] + sm[pr][i];
        g_LQT[(size_t)(v0 + i) * SNUM + sbase + p] = __logf(Q) - LOG5F;
    }
}

// ---------------- K3: token gather-sum -> all_emis, folding prior (l=0) / amax (l>0) ----------------
__global__ void k_gather(const int* __restrict__ stories, const float* __restrict__ pw) {
    int b = blockIdx.x, l = blockIdx.y;
    __shared__ int tok[WNUM];
    if (threadIdx.x < WNUM) tok[threadIdx.x] = stories[(b * LNUM + l) * WNUM + threadIdx.x];
    __syncthreads();
    int t = threadIdx.x;                 // 256 threads, 4 float4s each
    float plse = g_plse[0];
    float4* dst = reinterpret_cast<float4*>(g_allemis + ((size_t)l * BNUM + b) * SNUM);
    float4 acc[4];
    #pragma unroll
    for (int i = 0; i < 4; i++) {
        int j = (t + 256 * i) * 4;
        if (l == 0) {
            float4 q = *reinterpret_cast<const float4*>(&pw[j]);
            acc[i] = make_float4(q.x - plse, q.y - plse, q.z - plse, q.w - plse);
        } else {
            acc[i] = *reinterpret_cast<const float4*>(&g_amax[j]);
        }
    }
    #pragma unroll
    for (int w2 = 0; w2 < WNUM; w2++) {
        int tk = tok[w2];
        if (tk < VNUM) {
            const float4* row = reinterpret_cast<const float4*>(g_LQT + (size_t)tk * SNUM);
            #pragma unroll
            for (int i = 0; i < 4; i++) {
                float4 r = row[t + 256 * i];
                acc[i].x += r.x; acc[i].y += r.y; acc[i].z += r.z; acc[i].w += r.w;
            }
        }
    }
    #pragma unroll
    for (int i = 0; i < 4; i++) dst[t + 256 * i] = acc[i];
}

// ---------------- K5: forward recursion — 1024 threads, 4 contiguous states/thread ----------------
// Offsets {0,+1,-1,+16,-16,+256,+512}. ±1 = intra-thread + shfl-by-1 (thread
// edges land on x=3/x=0-type splits whose invalid cases sit exactly on x faces,
// P7==0 masks clamp garbage since 4 | 16). ±16/+256/+512 via LDS.128 from a
// zero-padded [halo16 | 4096 | halo512] buffer (faces masked by P7==0).
// amax folded into g_allemis (l>=1); prior folded into l=0. Block max: warp
// maxes -> red[32] at tail; each thread reduces red itself next iteration.
__global__ void __launch_bounds__(1024, 1)
k_forward(float* __restrict__ out) {
    __shared__ float sp[16 + SNUM + 512];   // [front16 | 4096 | back512]
    __shared__ float red[32];
    int b = blockIdx.x;
    int t = threadIdx.x;                 // 1024 threads, 4 contiguous states each
    int wid = t >> 5, lane = t & 31;
    int j0 = t * 4;

    // persistent transition rows (coalesced float4 loads, [k][s] layout)
    float p7r[7][4];
    #pragma unroll
    for (int k = 0; k < 7; k++) {
        float4 a = *reinterpret_cast<const float4*>(&g_P7[k * SNUM + j0]);
        p7r[k][0] = a.x; p7r[k][1] = a.y; p7r[k][2] = a.z; p7r[k][3] = a.w;
    }

    // zero halos once (never overwritten; P7==0 masks any read of them)
    if (t < 16)  sp[t] = 0.f;
    if (t < 512) sp[16 + SNUM + t] = 0.f;

    // l = 0: score0 already fully materialized by k_gather (em + prior - plse)
    float v[4];
    {
        float4 e = *reinterpret_cast<const float4*>(&g_allemis[(size_t)b * SNUM + j0]);
        v[0] = e.x; v[1] = e.y; v[2] = e.z; v[3] = e.w;
        *reinterpret_cast<float4*>(&out[(size_t)b * SNUM + j0]) = e;
    }
    {
        float lm = fmaxf(fmaxf(v[0], v[1]), fmaxf(v[2], v[3]));
        #pragma unroll
        for (int o = 16; o; o >>= 1) lm = fmaxf(lm, __shfl_xor_sync(0xffffffffu, lm, o));
        if (lane == 0) red[wid] = lm;
    }

    for (int l = 1; l < LNUM; l++) {
        __syncthreads();                 // red[] published; prev sp reads retired
        float m;
        {
            float4 r0 = *reinterpret_cast<const float4*>(&red[0]);
            float4 r1 = *reinterpret_cast<const float4*>(&red[4]);
            float4 r2 = *reinterpret_cast<const float4*>(&red[8]);
            float4 r3 = *reinterpret_cast<const float4*>(&red[12]);
            float4 r4 = *reinterpret_cast<const float4*>(&red[16]);
            float4 r5 = *reinterpret_cast<const float4*>(&red[20]);
            float4 r6 = *reinterpret_cast<const float4*>(&red[24]);
            float4 r7 = *reinterpret_cast<const float4*>(&red[28]);
            float m0 = fmaxf(fmaxf(r0.x, r0.y), fmaxf(r0.z, r0.w));
            float m1 = fmaxf(fmaxf(r1.x, r1.y), fmaxf(r1.z, r1.w));
            float m2 = fmaxf(fmaxf(r2.x, r2.y), fmaxf(r2.z, r2.w));
            float m3 = fmaxf(fmaxf(r3.x, r3.y), fmaxf(r3.z, r3.w));
            float m4 = fmaxf(fmaxf(r4.x, r4.y), fmaxf(r4.z, r4.w));
            float m5 = fmaxf(fmaxf(r5.x, r5.y), fmaxf(r5.z, r5.w));
            float m6 = fmaxf(fmaxf(r6.x, r6.y), fmaxf(r6.z, r6.w));
            float m7 = fmaxf(fmaxf(r7.x, r7.y), fmaxf(r7.z, r7.w));
            m = fmaxf(fmaxf(fmaxf(m0, m1), fmaxf(m2, m3)),
                      fmaxf(fmaxf(m4, m5), fmaxf(m6, m7)));
        }
        // phase A: sp = exp(score - m); publish; prefetch emissions; ±1 shfl
        float s0 = __expf(v[0] - m), s1 = __expf(v[1] - m);
        float s2 = __expf(v[2] - m), s3 = __expf(v[3] - m);
        *reinterpret_cast<float4*>(&sp[16 + j0]) = make_float4(s0, s1, s2, s3);
        float em[4];
        {
            float4 e = *reinterpret_cast<const float4*>(
                g_allemis + ((size_t)l * BNUM + b) * SNUM + j0);
            em[0] = e.x; em[1] = e.y; em[2] = e.z; em[3] = e.w;
        }
        float rgt = __shfl_down_sync(0xffffffffu, s0, 1);  // +1 across thread edge
        float lft = __shfl_up_sync(0xffffffffu, s3, 1);    // -1 across thread edge
        __syncthreads();                 // sp ready

        // phase B: ±16, +256, +512 via LDS.128; compute; publish max
        float4 u16 = *reinterpret_cast<const float4*>(&sp[16 + j0 + 16]);
        float4 d16 = *reinterpret_cast<const float4*>(&sp[16 + j0 - 16]);
        float4 u256 = *reinterpret_cast<const float4*>(&sp[16 + j0 + 256]);
        float4 u512 = *reinterpret_cast<const float4*>(&sp[16 + j0 + 512]);
        float sarr[4] = { s0, s1, s2, s3 };
        float n16[4]  = { u16.x, u16.y, u16.z, u16.w };
        float m16[4]  = { d16.x, d16.y, d16.z, d16.w };
        float n256[4] = { u256.x, u256.y, u256.z, u256.w };
        float n512[4] = { u512.x, u512.y, u512.z, u512.w };
        float lm = -INFINITY;
        #pragma unroll
        for (int st = 0; st < 4; st++) {
            float rn = (st < 3) ? sarr[st + 1] : rgt;
            float ln = (st > 0) ? sarr[st - 1] : lft;
            float acc = p7r[0][st] * sarr[st]
                      + p7r[1][st] * rn
                      + p7r[2][st] * ln
                      + p7r[3][st] * n16[st]
                      + p7r[4][st] * m16[st]
                      + p7r[5][st] * n256[st]
                      + p7r[6][st] * n512[st];
            v[st] = em[st] + __logf(acc) + m;   // amax already folded into em
            lm = fmaxf(lm, v[st]);
        }
        *reinterpret_cast<float4*>(out + ((size_t)l * BNUM + b) * SNUM + j0)
            = make_float4(v[0], v[1], v[2], v[3]);
        #pragma unroll
        for (int o = 16; o; o >>= 1) lm = fmaxf(lm, __shfl_xor_sync(0xffffffffu, lm, o));
        if (lane == 0) red[wid] = lm;
    }
}

// ---------------- launch ----------------
extern "C" void kernel_launch(void* const* d_in, const int* in_sizes, int n_in,
                              void* d_out, int out_size) {
    const int*   stories = nullptr;
    const float* trans_w = nullptr;
    const float* emis_w  = nullptr;
    const float* prior_w = nullptr;
    for (int i = 0; i < n_in; i++) {
        switch (in_sizes[i]) {
            case BNUM * LNUM * WNUM: stories = (const int*)d_in[i];   break; // 2048
            case SNUM * 7:           trans_w = (const float*)d_in[i]; break; // 28672
            case SNUM * VNUM:        emis_w  = (const float*)d_in[i]; break; // 8388608
            case SNUM:               prior_w = (const float*)d_in[i]; break; // 4096
            default: break; // story_length scalar
        }
    }
    float* out = (float*)d_out;

    k_prep<<<SNUM + 16 + 1, 256>>>(emis_w, trans_w, prior_w);
    k_smooth<<<dim3(VNUM / 32, ZDIM), 256>>>(emis_w);
    k_gather<<<dim3(BNUM, LNUM), 256>>>(stories, prior_w);
    k_forward<<<BNUM, 1024>>>(out);
}